// round 14
// baseline (speedup 1.0000x reference)
#include <cuda_runtime.h>
#include <cstdint>

#define B_   64
#define C_   384
#define N_   196
#define NH_  8
#define KD_  32
#define DV_  128
#define CQK  256
#define CV   1024
#define SCALE_ 0.17677669529663687f

// ---------------- scratch (device globals; no runtime allocation) ----------------
__device__ float g_q   [B_*CQK*N_];          // (b, h*32+kd, n)
__device__ float g_k   [B_*CQK*N_];          // (b, h*32+kd, n)
__device__ float g_v4  [B_*CV*N_];           // (b, c, n)   pre-conv V
__device__ float g_vloc[B_*CV*N_];           // depthwise-conv output
__device__ float g_attn[B_*NH_*N_*N_];       // (b, h, n, m)  reused in place
__device__ float g_oact[B_*CV*N_];           // relu(attn@v + vloc), (b, c, n)

// ===================== K1: fused QKV projection GEMM =====================
// Out(1536 x 196) = [qw;kw;vw](1536 x 384) @ x_b(384 x 196) + bias
// tiles: BM=128, BN=64, BK=16; 256 threads; 8x4 per thread
__global__ void __launch_bounds__(256) k_qkv(
    const float* __restrict__ x,
    const float* __restrict__ qw, const float* __restrict__ qb,
    const float* __restrict__ kw, const float* __restrict__ kb,
    const float* __restrict__ vw, const float* __restrict__ vb)
{
    const int b  = blockIdx.z;
    const int m0 = blockIdx.y * 128;
    const int n0 = blockIdx.x * 64;
    const int t  = threadIdx.x;
    __shared__ __align__(16) float As[16][132];
    __shared__ __align__(16) float Bs[16][68];
    float acc[8][4];
#pragma unroll
    for (int i = 0; i < 8; i++)
#pragma unroll
        for (int j = 0; j < 4; j++) acc[i][j] = 0.f;

    const int tym = t >> 4;   // 0..15
    const int txn = t & 15;   // 0..15
    const float* xb = x + (size_t)b * C_ * N_;

    for (int k0 = 0; k0 < C_; k0 += 16) {
#pragma unroll
        for (int i = 0; i < 8; i++) {
            int idx = t + 256 * i;
            int mm = idx >> 4;
            int kk = idx & 15;
            int m  = m0 + mm;
            const float* wr = (m < 256) ? (qw + (size_t)m * C_)
                             : (m < 512) ? (kw + (size_t)(m - 256) * C_)
                                         : (vw + (size_t)(m - 512) * C_);
            As[kk][mm] = wr[k0 + kk];
        }
#pragma unroll
        for (int i = 0; i < 4; i++) {
            int idx = t + 256 * i;
            int nn = idx & 63;
            int kk = idx >> 6;
            int n  = n0 + nn;
            Bs[kk][nn] = (n < N_) ? xb[(size_t)(k0 + kk) * N_ + n] : 0.f;
        }
        __syncthreads();
#pragma unroll
        for (int kk = 0; kk < 16; kk++) {
            float4 a0 = *(const float4*)&As[kk][tym * 8];
            float4 a1 = *(const float4*)&As[kk][tym * 8 + 4];
            float4 b0 = *(const float4*)&Bs[kk][txn * 4];
            float a[8] = {a0.x, a0.y, a0.z, a0.w, a1.x, a1.y, a1.z, a1.w};
            float bb[4] = {b0.x, b0.y, b0.z, b0.w};
#pragma unroll
            for (int i = 0; i < 8; i++)
#pragma unroll
                for (int j = 0; j < 4; j++) acc[i][j] += a[i] * bb[j];
        }
        __syncthreads();
    }

#pragma unroll
    for (int i = 0; i < 8; i++) {
        int m = m0 + tym * 8 + i;
        float bias; float* outp;
        if (m < 256)      { bias = qb[m];       outp = g_q  + ((size_t)b * CQK + m)        * N_; }
        else if (m < 512) { bias = kb[m - 256]; outp = g_k  + ((size_t)b * CQK + (m - 256)) * N_; }
        else              { bias = vb[m - 512]; outp = g_v4 + ((size_t)b * CV  + (m - 512)) * N_; }
#pragma unroll
        for (int j = 0; j < 4; j++) {
            int n = n0 + txn * 4 + j;
            if (n < N_) outp[n] = acc[i][j] + bias;
        }
    }
}

// ===================== K2: depthwise 3x3 conv on v4 =====================
__global__ void __launch_bounds__(224) k_dw(
    const float* __restrict__ vlw, const float* __restrict__ vlb)
{
    const int bc = blockIdx.x;          // b*1024 + c
    const int c  = bc & (CV - 1);
    __shared__ float plane[N_];
    __shared__ float w[9];
    __shared__ float wb;
    const int t = threadIdx.x;
    const float* src = g_v4 + (size_t)bc * N_;
    if (t < N_) plane[t] = src[t];
    if (t < 9)  w[t] = vlw[c * 9 + t];
    if (t == 0) wb = vlb[c];
    __syncthreads();
    if (t < N_) {
        int y = t / 14, xx = t % 14;
        float s = wb;
#pragma unroll
        for (int dy = -1; dy <= 1; dy++) {
            int yy = y + dy;
            if (yy < 0 || yy > 13) continue;
#pragma unroll
            for (int dx = -1; dx <= 1; dx++) {
                int xc = xx + dx;
                if (xc < 0 || xc > 13) continue;
                s += plane[yy * 14 + xc] * w[(dy + 1) * 3 + (dx + 1)];
            }
        }
        g_vloc[(size_t)bc * N_ + t] = s;
    }
}

// ===================== K3: attn = scale * q^T k + bias =====================
// per (b,h): q,k stored (kd, n); 64x64 tiles, K=32 single pass
__global__ void __launch_bounds__(256) k_qk(
    const float* __restrict__ bias_seg, const int* __restrict__ bias_idxs)
{
    const int bh = blockIdx.z;
    const int b = bh >> 3, h = bh & 7;
    const int r0 = blockIdx.y * 64;   // n (query)
    const int c0 = blockIdx.x * 64;   // m (key)
    const int t = threadIdx.x;
    __shared__ __align__(16) float As[32][68];
    __shared__ __align__(16) float Bs[32][68];
    const float* qp = g_q + ((size_t)b * CQK + h * KD_) * N_;
    const float* kp = g_k + ((size_t)b * CQK + h * KD_) * N_;
#pragma unroll
    for (int i = 0; i < 8; i++) {
        int idx = t + 256 * i;
        int cc = idx & 63;
        int kk = idx >> 6;
        int r = r0 + cc;
        As[kk][cc] = (r < N_) ? qp[(size_t)kk * N_ + r] : 0.f;
        int c = c0 + cc;
        Bs[kk][cc] = (c < N_) ? kp[(size_t)kk * N_ + c] : 0.f;
    }
    __syncthreads();
    const int tyr = t >> 4, txc = t & 15;
    float acc[4][4];
#pragma unroll
    for (int i = 0; i < 4; i++)
#pragma unroll
        for (int j = 0; j < 4; j++) acc[i][j] = 0.f;
#pragma unroll
    for (int kk = 0; kk < 32; kk++) {
        float4 a = *(const float4*)&As[kk][tyr * 4];
        float4 bb = *(const float4*)&Bs[kk][txc * 4];
        float av[4] = {a.x, a.y, a.z, a.w};
        float bv[4] = {bb.x, bb.y, bb.z, bb.w};
#pragma unroll
        for (int i = 0; i < 4; i++)
#pragma unroll
            for (int j = 0; j < 4; j++) acc[i][j] += av[i] * bv[j];
    }
    float* ap = g_attn + (size_t)bh * N_ * N_;
#pragma unroll
    for (int i = 0; i < 4; i++) {
        int n = r0 + tyr * 4 + i;
        if (n >= N_) continue;
#pragma unroll
        for (int j = 0; j < 4; j++) {
            int m = c0 + txc * 4 + j;
            if (m >= N_) continue;
            int bi = bias_idxs[n * N_ + m];
            ap[(size_t)n * N_ + m] = acc[i][j] * SCALE_ + bias_seg[h * N_ + bi];
        }
    }
}

// ============ K4: talking-heads-1 -> softmax -> talking-heads-2 (in place) ============
// one block per (b, n); all 8 head rows in smem
__global__ void __launch_bounds__(256) k_ths(
    const float* __restrict__ th1w, const float* __restrict__ th1b,
    const float* __restrict__ th2w, const float* __restrict__ th2b)
{
    const int n = blockIdx.x;
    const int b = blockIdx.y;
    const int t = threadIdx.x;
    __shared__ float sA[NH_][N_];
    __shared__ float sB[NH_][N_];
    __shared__ float w1[64], b1[8], w2[64], b2[8];
    if (t < 64) { w1[t] = th1w[t]; w2[t] = th2w[t]; }
    if (t < 8)  { b1[t] = th1b[t]; b2[t] = th2b[t]; }
    const size_t base = ((size_t)b * NH_) * N_ * N_ + (size_t)n * N_;
    for (int idx = t; idx < NH_ * N_; idx += 256) {
        int h = idx / N_, m = idx % N_;
        sA[h][m] = g_attn[base + (size_t)h * N_ * N_ + m];
    }
    __syncthreads();
    for (int idx = t; idx < NH_ * N_; idx += 256) {
        int h = idx / N_, m = idx % N_;
        float s = b1[h];
#pragma unroll
        for (int g = 0; g < 8; g++) s += w1[h * 8 + g] * sA[g][m];
        sB[h][m] = s;
    }
    __syncthreads();
    {   // warp w handles head w
        const int h = t >> 5, lane = t & 31;
        float mx = -1e30f;
        for (int m = lane; m < N_; m += 32) mx = fmaxf(mx, sB[h][m]);
#pragma unroll
        for (int o = 16; o; o >>= 1) mx = fmaxf(mx, __shfl_xor_sync(0xffffffffu, mx, o));
        float sum = 0.f;
        for (int m = lane; m < N_; m += 32) {
            float e = __expf(sB[h][m] - mx);
            sB[h][m] = e;
            sum += e;
        }
#pragma unroll
        for (int o = 16; o; o >>= 1) sum += __shfl_xor_sync(0xffffffffu, sum, o);
        float inv = 1.f / sum;
        for (int m = lane; m < N_; m += 32) sB[h][m] *= inv;
    }
    __syncthreads();
    for (int idx = t; idx < NH_ * N_; idx += 256) {
        int h = idx / N_, m = idx % N_;
        float s = b2[h];
#pragma unroll
        for (int g = 0; g < 8; g++) s += w2[h * 8 + g] * sB[g][m];
        g_attn[base + (size_t)h * N_ * N_ + m] = s;
    }
}

// ===================== K5: o = attn @ v, + vloc, relu =====================
// per (b,h): O(128 x 196) = V(128 x 196_m) @ attn^T(196_m x 196_n)
__global__ void __launch_bounds__(256) k_av()
{
    const int bh = blockIdx.y;
    const int b = bh >> 3, h = bh & 7;
    const int n0 = blockIdx.x * 64;
    const int t = threadIdx.x;
    __shared__ __align__(16) float As[16][132];
    __shared__ __align__(16) float Bs[16][68];
    float acc[8][4];
#pragma unroll
    for (int i = 0; i < 8; i++)
#pragma unroll
        for (int j = 0; j < 4; j++) acc[i][j] = 0.f;
    const int tym = t >> 4, txn = t & 15;
    const float* vp = g_v4  + ((size_t)b * CV + h * DV_) * N_;
    const float* ap = g_attn + (size_t)bh * N_ * N_;

    for (int k0 = 0; k0 < 208; k0 += 16) {
#pragma unroll
        for (int i = 0; i < 8; i++) {
            int idx = t + 256 * i;
            int mm = idx >> 4;     // d
            int kk = idx & 15;
            int k = k0 + kk;
            As[kk][mm] = (k < N_) ? vp[(size_t)mm * N_ + k] : 0.f;
        }
#pragma unroll
        for (int i = 0; i < 4; i++) {
            int idx = t + 256 * i;
            int nn = idx >> 4;     // 0..63
            int kk = idx & 15;
            int n = n0 + nn;
            int k = k0 + kk;
            Bs[kk][nn] = (n < N_ && k < N_) ? ap[(size_t)n * N_ + k] : 0.f;
        }
        __syncthreads();
#pragma unroll
        for (int kk = 0; kk < 16; kk++) {
            float4 a0 = *(const float4*)&As[kk][tym * 8];
            float4 a1 = *(const float4*)&As[kk][tym * 8 + 4];
            float4 b0 = *(const float4*)&Bs[kk][txn * 4];
            float a[8] = {a0.x, a0.y, a0.z, a0.w, a1.x, a1.y, a1.z, a1.w};
            float bb[4] = {b0.x, b0.y, b0.z, b0.w};
#pragma unroll
            for (int i = 0; i < 8; i++)
#pragma unroll
                for (int j = 0; j < 4; j++) acc[i][j] += a[i] * bb[j];
        }
        __syncthreads();
    }

#pragma unroll
    for (int i = 0; i < 8; i++) {
        int d = tym * 8 + i;
        int c = h * DV_ + d;
        const float* vl = g_vloc + ((size_t)b * CV + c) * N_;
        float* op       = g_oact + ((size_t)b * CV + c) * N_;
#pragma unroll
        for (int j = 0; j < 4; j++) {
            int n = n0 + txn * 4 + j;
            if (n < N_) {
                float v = acc[i][j] + vl[n];
                op[n] = v > 0.f ? v : 0.f;
            }
        }
    }
}

// ===================== K6: output projection GEMM =====================
// Out(384 x 196) = projw(384 x 1024) @ oact_b(1024 x 196) + projb
__global__ void __launch_bounds__(256) k_proj(
    const float* __restrict__ pw, const float* __restrict__ pb,
    float* __restrict__ out)
{
    const int b  = blockIdx.z;
    const int m0 = blockIdx.y * 128;
    const int n0 = blockIdx.x * 64;
    const int t  = threadIdx.x;
    __shared__ __align__(16) float As[16][132];
    __shared__ __align__(16) float Bs[16][68];
    float acc[8][4];
#pragma unroll
    for (int i = 0; i < 8; i++)
#pragma unroll
        for (int j = 0; j < 4; j++) acc[i][j] = 0.f;
    const int tym = t >> 4, txn = t & 15;
    const float* xb = g_oact + (size_t)b * CV * N_;

    for (int k0 = 0; k0 < CV; k0 += 16) {
#pragma unroll
        for (int i = 0; i < 8; i++) {
            int idx = t + 256 * i;
            int mm = idx >> 4;
            int kk = idx & 15;
            As[kk][mm] = pw[(size_t)(m0 + mm) * CV + k0 + kk];
        }
#pragma unroll
        for (int i = 0; i < 4; i++) {
            int idx = t + 256 * i;
            int nn = idx & 63;
            int kk = idx >> 6;
            int n  = n0 + nn;
            Bs[kk][nn] = (n < N_) ? xb[(size_t)(k0 + kk) * N_ + n] : 0.f;
        }
        __syncthreads();
#pragma unroll
        for (int kk = 0; kk < 16; kk++) {
            float4 a0 = *(const float4*)&As[kk][tym * 8];
            float4 a1 = *(const float4*)&As[kk][tym * 8 + 4];
            float4 b0 = *(const float4*)&Bs[kk][txn * 4];
            float a[8] = {a0.x, a0.y, a0.z, a0.w, a1.x, a1.y, a1.z, a1.w};
            float bb[4] = {b0.x, b0.y, b0.z, b0.w};
#pragma unroll
            for (int i = 0; i < 8; i++)
#pragma unroll
                for (int j = 0; j < 4; j++) acc[i][j] += a[i] * bb[j];
        }
        __syncthreads();
    }

#pragma unroll
    for (int i = 0; i < 8; i++) {
        int m = m0 + tym * 8 + i;
        float bias = pb[m];
        float* op = out + ((size_t)b * C_ + m) * N_;
#pragma unroll
        for (int j = 0; j < 4; j++) {
            int n = n0 + txn * 4 + j;
            if (n < N_) op[n] = acc[i][j] + bias;
        }
    }
}

// ===================== launch =====================
extern "C" void kernel_launch(void* const* d_in, const int* in_sizes, int n_in,
                              void* d_out, int out_size)
{
    const float* x    = (const float*)d_in[0];
    const float* qw   = (const float*)d_in[1];
    const float* qb   = (const float*)d_in[2];
    const float* kw   = (const float*)d_in[3];
    const float* kb   = (const float*)d_in[4];
    const float* vw   = (const float*)d_in[5];
    const float* vb   = (const float*)d_in[6];
    const float* vlw  = (const float*)d_in[7];
    const float* vlb  = (const float*)d_in[8];
    const float* th1w = (const float*)d_in[9];
    const float* th1b = (const float*)d_in[10];
    const float* th2w = (const float*)d_in[11];
    const float* th2b = (const float*)d_in[12];
    const float* pw   = (const float*)d_in[13];
    const float* pb   = (const float*)d_in[14];
    const float* bseg = (const float*)d_in[15];
    const int*   bidx = (const int*)d_in[16];
    float* out = (float*)d_out;

    k_qkv <<<dim3(4, 12, B_), 256>>>(x, qw, qb, kw, kb, vw, vb);
    k_dw  <<<dim3(B_ * CV), 224>>>(vlw, vlb);
    k_qk  <<<dim3(4, 4, B_ * NH_), 256>>>(bseg, bidx);
    k_ths <<<dim3(N_, B_), 256>>>(th1w, th1b, th2w, th2b);
    k_av  <<<dim3(4, B_ * NH_), 256>>>();
    k_proj<<<dim3(4, 3, B_), 256>>>(pw, pb, out);
}

// round 15
// speedup vs baseline: 1.0009x; 1.0009x over previous
#include <cuda_runtime.h>
#include <cstdint>

#define B_   64
#define C_   384
#define N_   196
#define NH_  8
#define KD_  32
#define DV_  128
#define CQK  256
#define CV   1024
#define SCALE_ 0.17677669529663687f

// ---------------- scratch (device globals; no runtime allocation) ----------------
__device__ float g_q   [B_*CQK*N_];          // (b, h*32+kd, n)
__device__ float g_k   [B_*CQK*N_];          // (b, h*32+kd, n)
__device__ float g_v4  [B_*CV*N_];           // (b, c, n)   pre-conv V
__device__ float g_vloc[B_*CV*N_];           // depthwise-conv output
__device__ float g_attn[B_*NH_*N_*N_];       // (b, h, n, m)  reused in place
__device__ float g_oact[B_*CV*N_];           // relu(attn@v + vloc), (b, c, n)

// ===================== K1: fused QKV projection GEMM =====================
// Out(1536 x 196) = [qw;kw;vw](1536 x 384) @ x_b(384 x 196) + bias
// tiles: BM=128, BN=64, BK=16; 256 threads; 8x4 per thread
__global__ void __launch_bounds__(256) k_qkv(
    const float* __restrict__ x,
    const float* __restrict__ qw, const float* __restrict__ qb,
    const float* __restrict__ kw, const float* __restrict__ kb,
    const float* __restrict__ vw, const float* __restrict__ vb)
{
    const int b  = blockIdx.z;
    const int m0 = blockIdx.y * 128;
    const int n0 = blockIdx.x * 64;
    const int t  = threadIdx.x;
    __shared__ __align__(16) float As[16][132];
    __shared__ __align__(16) float Bs[16][68];
    float acc[8][4];
#pragma unroll
    for (int i = 0; i < 8; i++)
#pragma unroll
        for (int j = 0; j < 4; j++) acc[i][j] = 0.f;

    const int tym = t >> 4;   // 0..15
    const int txn = t & 15;   // 0..15
    const float* xb = x + (size_t)b * C_ * N_;

    for (int k0 = 0; k0 < C_; k0 += 16) {
#pragma unroll
        for (int i = 0; i < 8; i++) {
            int idx = t + 256 * i;
            int mm = idx >> 4;
            int kk = idx & 15;
            int m  = m0 + mm;
            const float* wr = (m < 256) ? (qw + (size_t)m * C_)
                             : (m < 512) ? (kw + (size_t)(m - 256) * C_)
                                         : (vw + (size_t)(m - 512) * C_);
            As[kk][mm] = wr[k0 + kk];
        }
#pragma unroll
        for (int i = 0; i < 4; i++) {
            int idx = t + 256 * i;
            int nn = idx & 63;
            int kk = idx >> 6;
            int n  = n0 + nn;
            Bs[kk][nn] = (n < N_) ? xb[(size_t)(k0 + kk) * N_ + n] : 0.f;
        }
        __syncthreads();
#pragma unroll
        for (int kk = 0; kk < 16; kk++) {
            float4 a0 = *(const float4*)&As[kk][tym * 8];
            float4 a1 = *(const float4*)&As[kk][tym * 8 + 4];
            float4 b0 = *(const float4*)&Bs[kk][txn * 4];
            float a[8] = {a0.x, a0.y, a0.z, a0.w, a1.x, a1.y, a1.z, a1.w};
            float bb[4] = {b0.x, b0.y, b0.z, b0.w};
#pragma unroll
            for (int i = 0; i < 8; i++)
#pragma unroll
                for (int j = 0; j < 4; j++) acc[i][j] += a[i] * bb[j];
        }
        __syncthreads();
    }

#pragma unroll
    for (int i = 0; i < 8; i++) {
        int m = m0 + tym * 8 + i;
        float bias; float* outp;
        if (m < 256)      { bias = qb[m];       outp = g_q  + ((size_t)b * CQK + m)        * N_; }
        else if (m < 512) { bias = kb[m - 256]; outp = g_k  + ((size_t)b * CQK + (m - 256)) * N_; }
        else              { bias = vb[m - 512]; outp = g_v4 + ((size_t)b * CV  + (m - 512)) * N_; }
#pragma unroll
        for (int j = 0; j < 4; j++) {
            int n = n0 + txn * 4 + j;
            if (n < N_) outp[n] = acc[i][j] + bias;
        }
    }
}

// ===================== K2: depthwise 3x3 conv on v4 =====================
__global__ void __launch_bounds__(224) k_dw(
    const float* __restrict__ vlw, const float* __restrict__ vlb)
{
    const int bc = blockIdx.x;          // b*1024 + c
    const int c  = bc & (CV - 1);
    __shared__ float plane[N_];
    __shared__ float w[9];
    __shared__ float wb;
    const int t = threadIdx.x;
    const float* src = g_v4 + (size_t)bc * N_;
    if (t < N_) plane[t] = src[t];
    if (t < 9)  w[t] = vlw[c * 9 + t];
    if (t == 0) wb = vlb[c];
    __syncthreads();
    if (t < N_) {
        int y = t / 14, xx = t % 14;
        float s = wb;
#pragma unroll
        for (int dy = -1; dy <= 1; dy++) {
            int yy = y + dy;
            if (yy < 0 || yy > 13) continue;
#pragma unroll
            for (int dx = -1; dx <= 1; dx++) {
                int xc = xx + dx;
                if (xc < 0 || xc > 13) continue;
                s += plane[yy * 14 + xc] * w[(dy + 1) * 3 + (dx + 1)];
            }
        }
        g_vloc[(size_t)bc * N_ + t] = s;
    }
}

// ===================== K3: attn = scale * q^T k + bias =====================
// per (b,h): q,k stored (kd, n); 64x64 tiles, K=32 single pass
__global__ void __launch_bounds__(256) k_qk(
    const float* __restrict__ bias_seg, const int* __restrict__ bias_idxs)
{
    const int bh = blockIdx.z;
    const int b = bh >> 3, h = bh & 7;
    const int r0 = blockIdx.y * 64;   // n (query)
    const int c0 = blockIdx.x * 64;   // m (key)
    const int t = threadIdx.x;
    __shared__ __align__(16) float As[32][68];
    __shared__ __align__(16) float Bs[32][68];
    const float* qp = g_q + ((size_t)b * CQK + h * KD_) * N_;
    const float* kp = g_k + ((size_t)b * CQK + h * KD_) * N_;
#pragma unroll
    for (int i = 0; i < 8; i++) {
        int idx = t + 256 * i;
        int cc = idx & 63;
        int kk = idx >> 6;
        int r = r0 + cc;
        As[kk][cc] = (r < N_) ? qp[(size_t)kk * N_ + r] : 0.f;
        int c = c0 + cc;
        Bs[kk][cc] = (c < N_) ? kp[(size_t)kk * N_ + c] : 0.f;
    }
    __syncthreads();
    const int tyr = t >> 4, txc = t & 15;
    float acc[4][4];
#pragma unroll
    for (int i = 0; i < 4; i++)
#pragma unroll
        for (int j = 0; j < 4; j++) acc[i][j] = 0.f;
#pragma unroll
    for (int kk = 0; kk < 32; kk++) {
        float4 a = *(const float4*)&As[kk][tyr * 4];
        float4 bb = *(const float4*)&Bs[kk][txc * 4];
        float av[4] = {a.x, a.y, a.z, a.w};
        float bv[4] = {bb.x, bb.y, bb.z, bb.w};
#pragma unroll
        for (int i = 0; i < 4; i++)
#pragma unroll
            for (int j = 0; j < 4; j++) acc[i][j] += av[i] * bv[j];
    }
    float* ap = g_attn + (size_t)bh * N_ * N_;
#pragma unroll
    for (int i = 0; i < 4; i++) {
        int n = r0 + tyr * 4 + i;
        if (n >= N_) continue;
#pragma unroll
        for (int j = 0; j < 4; j++) {
            int m = c0 + txc * 4 + j;
            if (m >= N_) continue;
            int bi = bias_idxs[n * N_ + m];
            ap[(size_t)n * N_ + m] = acc[i][j] * SCALE_ + bias_seg[h * N_ + bi];
        }
    }
}

// ============ K4: talking-heads-1 -> softmax -> talking-heads-2 (in place) ============
// one block per (b, n); all 8 head rows in smem
__global__ void __launch_bounds__(256) k_ths(
    const float* __restrict__ th1w, const float* __restrict__ th1b,
    const float* __restrict__ th2w, const float* __restrict__ th2b)
{
    const int n = blockIdx.x;
    const int b = blockIdx.y;
    const int t = threadIdx.x;
    __shared__ float sA[NH_][N_];
    __shared__ float sB[NH_][N_];
    __shared__ float w1[64], b1[8], w2[64], b2[8];
    if (t < 64) { w1[t] = th1w[t]; w2[t] = th2w[t]; }
    if (t < 8)  { b1[t] = th1b[t]; b2[t] = th2b[t]; }
    const size_t base = ((size_t)b * NH_) * N_ * N_ + (size_t)n * N_;
    for (int idx = t; idx < NH_ * N_; idx += 256) {
        int h = idx / N_, m = idx % N_;
        sA[h][m] = g_attn[base + (size_t)h * N_ * N_ + m];
    }
    __syncthreads();
    for (int idx = t; idx < NH_ * N_; idx += 256) {
        int h = idx / N_, m = idx % N_;
        float s = b1[h];
#pragma unroll
        for (int g = 0; g < 8; g++) s += w1[h * 8 + g] * sA[g][m];
        sB[h][m] = s;
    }
    __syncthreads();
    {   // warp w handles head w
        const int h = t >> 5, lane = t & 31;
        float mx = -1e30f;
        for (int m = lane; m < N_; m += 32) mx = fmaxf(mx, sB[h][m]);
#pragma unroll
        for (int o = 16; o; o >>= 1) mx = fmaxf(mx, __shfl_xor_sync(0xffffffffu, mx, o));
        float sum = 0.f;
        for (int m = lane; m < N_; m += 32) {
            float e = __expf(sB[h][m] - mx);
            sB[h][m] = e;
            sum += e;
        }
#pragma unroll
        for (int o = 16; o; o >>= 1) sum += __shfl_xor_sync(0xffffffffu, sum, o);
        float inv = 1.f / sum;
        for (int m = lane; m < N_; m += 32) sB[h][m] *= inv;
    }
    __syncthreads();
    for (int idx = t; idx < NH_ * N_; idx += 256) {
        int h = idx / N_, m = idx % N_;
        float s = b2[h];
#pragma unroll
        for (int g = 0; g < 8; g++) s += w2[h * 8 + g] * sB[g][m];
        g_attn[base + (size_t)h * N_ * N_ + m] = s;
    }
}

// ===================== K5: o = attn @ v, + vloc, relu =====================
// per (b,h): O(128 x 196) = V(128 x 196_m) @ attn^T(196_m x 196_n)
__global__ void __launch_bounds__(256) k_av()
{
    const int bh = blockIdx.y;
    const int b = bh >> 3, h = bh & 7;
    const int n0 = blockIdx.x * 64;
    const int t = threadIdx.x;
    __shared__ __align__(16) float As[16][132];
    __shared__ __align__(16) float Bs[16][68];
    float acc[8][4];
#pragma unroll
    for (int i = 0; i < 8; i++)
#pragma unroll
        for (int j = 0; j < 4; j++) acc[i][j] = 0.f;
    const int tym = t >> 4, txn = t & 15;
    const float* vp = g_v4  + ((size_t)b * CV + h * DV_) * N_;
    const float* ap = g_attn + (size_t)bh * N_ * N_;

    for (int k0 = 0; k0 < 208; k0 += 16) {
#pragma unroll
        for (int i = 0; i < 8; i++) {
            int idx = t + 256 * i;
            int mm = idx >> 4;     // d
            int kk = idx & 15;
            int k = k0 + kk;
            As[kk][mm] = (k < N_) ? vp[(size_t)mm * N_ + k] : 0.f;
        }
#pragma unroll
        for (int i = 0; i < 4; i++) {
            int idx = t + 256 * i;
            int nn = idx >> 4;     // 0..63
            int kk = idx & 15;
            int n = n0 + nn;
            int k = k0 + kk;
            Bs[kk][nn] = (n < N_ && k < N_) ? ap[(size_t)n * N_ + k] : 0.f;
        }
        __syncthreads();
#pragma unroll
        for (int kk = 0; kk < 16; kk++) {
            float4 a0 = *(const float4*)&As[kk][tym * 8];
            float4 a1 = *(const float4*)&As[kk][tym * 8 + 4];
            float4 b0 = *(const float4*)&Bs[kk][txn * 4];
            float a[8] = {a0.x, a0.y, a0.z, a0.w, a1.x, a1.y, a1.z, a1.w};
            float bb[4] = {b0.x, b0.y, b0.z, b0.w};
#pragma unroll
            for (int i = 0; i < 8; i++)
#pragma unroll
                for (int j = 0; j < 4; j++) acc[i][j] += a[i] * bb[j];
        }
        __syncthreads();
    }

#pragma unroll
    for (int i = 0; i < 8; i++) {
        int d = tym * 8 + i;
        int c = h * DV_ + d;
        const float* vl = g_vloc + ((size_t)b * CV + c) * N_;
        float* op       = g_oact + ((size_t)b * CV + c) * N_;
#pragma unroll
        for (int j = 0; j < 4; j++) {
            int n = n0 + txn * 4 + j;
            if (n < N_) {
                float v = acc[i][j] + vl[n];
                op[n] = v > 0.f ? v : 0.f;
            }
        }
    }
}

// ===================== K6: output projection GEMM =====================
// Out(384 x 196) = projw(384 x 1024) @ oact_b(1024 x 196) + projb
__global__ void __launch_bounds__(256) k_proj(
    const float* __restrict__ pw, const float* __restrict__ pb,
    float* __restrict__ out)
{
    const int b  = blockIdx.z;
    const int m0 = blockIdx.y * 128;
    const int n0 = blockIdx.x * 64;
    const int t  = threadIdx.x;
    __shared__ __align__(16) float As[16][132];
    __shared__ __align__(16) float Bs[16][68];
    float acc[8][4];
#pragma unroll
    for (int i = 0; i < 8; i++)
#pragma unroll
        for (int j = 0; j < 4; j++) acc[i][j] = 0.f;
    const int tym = t >> 4, txn = t & 15;
    const float* xb = g_oact + (size_t)b * CV * N_;

    for (int k0 = 0; k0 < CV; k0 += 16) {
#pragma unroll
        for (int i = 0; i < 8; i++) {
            int idx = t + 256 * i;
            int mm = idx >> 4;
            int kk = idx & 15;
            As[kk][mm] = pw[(size_t)(m0 + mm) * CV + k0 + kk];
        }
#pragma unroll
        for (int i = 0; i < 4; i++) {
            int idx = t + 256 * i;
            int nn = idx & 63;
            int kk = idx >> 6;
            int n  = n0 + nn;
            Bs[kk][nn] = (n < N_) ? xb[(size_t)(k0 + kk) * N_ + n] : 0.f;
        }
        __syncthreads();
#pragma unroll
        for (int kk = 0; kk < 16; kk++) {
            float4 a0 = *(const float4*)&As[kk][tym * 8];
            float4 a1 = *(const float4*)&As[kk][tym * 8 + 4];
            float4 b0 = *(const float4*)&Bs[kk][txn * 4];
            float a[8] = {a0.x, a0.y, a0.z, a0.w, a1.x, a1.y, a1.z, a1.w};
            float bb[4] = {b0.x, b0.y, b0.z, b0.w};
#pragma unroll
            for (int i = 0; i < 8; i++)
#pragma unroll
                for (int j = 0; j < 4; j++) acc[i][j] += a[i] * bb[j];
        }
        __syncthreads();
    }

#pragma unroll
    for (int i = 0; i < 8; i++) {
        int m = m0 + tym * 8 + i;
        float bias = pb[m];
        float* op = out + ((size_t)b * C_ + m) * N_;
#pragma unroll
        for (int j = 0; j < 4; j++) {
            int n = n0 + txn * 4 + j;
            if (n < N_) op[n] = acc[i][j] + bias;
        }
    }
}

// ===================== launch =====================
extern "C" void kernel_launch(void* const* d_in, const int* in_sizes, int n_in,
                              void* d_out, int out_size)
{
    const float* x    = (const float*)d_in[0];
    const float* qw   = (const float*)d_in[1];
    const float* qb   = (const float*)d_in[2];
    const float* kw   = (const float*)d_in[3];
    const float* kb   = (const float*)d_in[4];
    const float* vw   = (const float*)d_in[5];
    const float* vb   = (const float*)d_in[6];
    const float* vlw  = (const float*)d_in[7];
    const float* vlb  = (const float*)d_in[8];
    const float* th1w = (const float*)d_in[9];
    const float* th1b = (const float*)d_in[10];
    const float* th2w = (const float*)d_in[11];
    const float* th2b = (const float*)d_in[12];
    const float* pw   = (const float*)d_in[13];
    const float* pb   = (const float*)d_in[14];
    const float* bseg = (const float*)d_in[15];
    const int*   bidx = (const int*)d_in[16];
    float* out = (float*)d_out;

    k_qkv <<<dim3(4, 12, B_), 256>>>(x, qw, qb, kw, kb, vw, vb);
    k_dw  <<<dim3(B_ * CV), 224>>>(vlw, vlb);
    k_qk  <<<dim3(4, 4, B_ * NH_), 256>>>(bseg, bidx);
    k_ths <<<dim3(N_, B_), 256>>>(th1w, th1b, th2w, th2b);
    k_av  <<<dim3(4, B_ * NH_), 256>>>();
    k_proj<<<dim3(4, 3, B_), 256>>>(pw, pb, out);
}

// round 16
// speedup vs baseline: 1.0016x; 1.0007x over previous
#include <cuda_runtime.h>
#include <cstdint>

#define B_   64
#define C_   384
#define N_   196
#define NH_  8
#define KD_  32
#define DV_  128
#define CQK  256
#define CV   1024
#define SCALE_ 0.17677669529663687f

// ---------------- scratch (device globals; no runtime allocation) ----------------
__device__ float g_q   [B_*CQK*N_];          // (b, h*32+kd, n)
__device__ float g_k   [B_*CQK*N_];          // (b, h*32+kd, n)
__device__ float g_v4  [B_*CV*N_];           // (b, c, n)   pre-conv V
__device__ float g_vloc[B_*CV*N_];           // depthwise-conv output
__device__ float g_attn[B_*NH_*N_*N_];       // (b, h, n, m)  reused in place
__device__ float g_oact[B_*CV*N_];           // relu(attn@v + vloc), (b, c, n)

// ===================== K1: fused QKV projection GEMM =====================
// Out(1536 x 196) = [qw;kw;vw](1536 x 384) @ x_b(384 x 196) + bias
// tiles: BM=128, BN=64, BK=16; 256 threads; 8x4 per thread
__global__ void __launch_bounds__(256) k_qkv(
    const float* __restrict__ x,
    const float* __restrict__ qw, const float* __restrict__ qb,
    const float* __restrict__ kw, const float* __restrict__ kb,
    const float* __restrict__ vw, const float* __restrict__ vb)
{
    const int b  = blockIdx.z;
    const int m0 = blockIdx.y * 128;
    const int n0 = blockIdx.x * 64;
    const int t  = threadIdx.x;
    __shared__ __align__(16) float As[16][132];
    __shared__ __align__(16) float Bs[16][68];
    float acc[8][4];
#pragma unroll
    for (int i = 0; i < 8; i++)
#pragma unroll
        for (int j = 0; j < 4; j++) acc[i][j] = 0.f;

    const int tym = t >> 4;   // 0..15
    const int txn = t & 15;   // 0..15
    const float* xb = x + (size_t)b * C_ * N_;

    for (int k0 = 0; k0 < C_; k0 += 16) {
#pragma unroll
        for (int i = 0; i < 8; i++) {
            int idx = t + 256 * i;
            int mm = idx >> 4;
            int kk = idx & 15;
            int m  = m0 + mm;
            const float* wr = (m < 256) ? (qw + (size_t)m * C_)
                             : (m < 512) ? (kw + (size_t)(m - 256) * C_)
                                         : (vw + (size_t)(m - 512) * C_);
            As[kk][mm] = wr[k0 + kk];
        }
#pragma unroll
        for (int i = 0; i < 4; i++) {
            int idx = t + 256 * i;
            int nn = idx & 63;
            int kk = idx >> 6;
            int n  = n0 + nn;
            Bs[kk][nn] = (n < N_) ? xb[(size_t)(k0 + kk) * N_ + n] : 0.f;
        }
        __syncthreads();
#pragma unroll
        for (int kk = 0; kk < 16; kk++) {
            float4 a0 = *(const float4*)&As[kk][tym * 8];
            float4 a1 = *(const float4*)&As[kk][tym * 8 + 4];
            float4 b0 = *(const float4*)&Bs[kk][txn * 4];
            float a[8] = {a0.x, a0.y, a0.z, a0.w, a1.x, a1.y, a1.z, a1.w};
            float bb[4] = {b0.x, b0.y, b0.z, b0.w};
#pragma unroll
            for (int i = 0; i < 8; i++)
#pragma unroll
                for (int j = 0; j < 4; j++) acc[i][j] += a[i] * bb[j];
        }
        __syncthreads();
    }

#pragma unroll
    for (int i = 0; i < 8; i++) {
        int m = m0 + tym * 8 + i;
        float bias; float* outp;
        if (m < 256)      { bias = qb[m];       outp = g_q  + ((size_t)b * CQK + m)        * N_; }
        else if (m < 512) { bias = kb[m - 256]; outp = g_k  + ((size_t)b * CQK + (m - 256)) * N_; }
        else              { bias = vb[m - 512]; outp = g_v4 + ((size_t)b * CV  + (m - 512)) * N_; }
#pragma unroll
        for (int j = 0; j < 4; j++) {
            int n = n0 + txn * 4 + j;
            if (n < N_) outp[n] = acc[i][j] + bias;
        }
    }
}

// ===================== K2: depthwise 3x3 conv on v4 =====================
__global__ void __launch_bounds__(224) k_dw(
    const float* __restrict__ vlw, const float* __restrict__ vlb)
{
    const int bc = blockIdx.x;          // b*1024 + c
    const int c  = bc & (CV - 1);
    __shared__ float plane[N_];
    __shared__ float w[9];
    __shared__ float wb;
    const int t = threadIdx.x;
    const float* src = g_v4 + (size_t)bc * N_;
    if (t < N_) plane[t] = src[t];
    if (t < 9)  w[t] = vlw[c * 9 + t];
    if (t == 0) wb = vlb[c];
    __syncthreads();
    if (t < N_) {
        int y = t / 14, xx = t % 14;
        float s = wb;
#pragma unroll
        for (int dy = -1; dy <= 1; dy++) {
            int yy = y + dy;
            if (yy < 0 || yy > 13) continue;
#pragma unroll
            for (int dx = -1; dx <= 1; dx++) {
                int xc = xx + dx;
                if (xc < 0 || xc > 13) continue;
                s += plane[yy * 14 + xc] * w[(dy + 1) * 3 + (dx + 1)];
            }
        }
        g_vloc[(size_t)bc * N_ + t] = s;
    }
}

// ===================== K3: attn = scale * q^T k + bias =====================
// per (b,h): q,k stored (kd, n); 64x64 tiles, K=32 single pass
__global__ void __launch_bounds__(256) k_qk(
    const float* __restrict__ bias_seg, const int* __restrict__ bias_idxs)
{
    const int bh = blockIdx.z;
    const int b = bh >> 3, h = bh & 7;
    const int r0 = blockIdx.y * 64;   // n (query)
    const int c0 = blockIdx.x * 64;   // m (key)
    const int t = threadIdx.x;
    __shared__ __align__(16) float As[32][68];
    __shared__ __align__(16) float Bs[32][68];
    const float* qp = g_q + ((size_t)b * CQK + h * KD_) * N_;
    const float* kp = g_k + ((size_t)b * CQK + h * KD_) * N_;
#pragma unroll
    for (int i = 0; i < 8; i++) {
        int idx = t + 256 * i;
        int cc = idx & 63;
        int kk = idx >> 6;
        int r = r0 + cc;
        As[kk][cc] = (r < N_) ? qp[(size_t)kk * N_ + r] : 0.f;
        int c = c0 + cc;
        Bs[kk][cc] = (c < N_) ? kp[(size_t)kk * N_ + c] : 0.f;
    }
    __syncthreads();
    const int tyr = t >> 4, txc = t & 15;
    float acc[4][4];
#pragma unroll
    for (int i = 0; i < 4; i++)
#pragma unroll
        for (int j = 0; j < 4; j++) acc[i][j] = 0.f;
#pragma unroll
    for (int kk = 0; kk < 32; kk++) {
        float4 a = *(const float4*)&As[kk][tyr * 4];
        float4 bb = *(const float4*)&Bs[kk][txc * 4];
        float av[4] = {a.x, a.y, a.z, a.w};
        float bv[4] = {bb.x, bb.y, bb.z, bb.w};
#pragma unroll
        for (int i = 0; i < 4; i++)
#pragma unroll
            for (int j = 0; j < 4; j++) acc[i][j] += av[i] * bv[j];
    }
    float* ap = g_attn + (size_t)bh * N_ * N_;
#pragma unroll
    for (int i = 0; i < 4; i++) {
        int n = r0 + tyr * 4 + i;
        if (n >= N_) continue;
#pragma unroll
        for (int j = 0; j < 4; j++) {
            int m = c0 + txc * 4 + j;
            if (m >= N_) continue;
            int bi = bias_idxs[n * N_ + m];
            ap[(size_t)n * N_ + m] = acc[i][j] * SCALE_ + bias_seg[h * N_ + bi];
        }
    }
}

// ============ K4: talking-heads-1 -> softmax -> talking-heads-2 (in place) ============
// one block per (b, n); all 8 head rows in smem
__global__ void __launch_bounds__(256) k_ths(
    const float* __restrict__ th1w, const float* __restrict__ th1b,
    const float* __restrict__ th2w, const float* __restrict__ th2b)
{
    const int n = blockIdx.x;
    const int b = blockIdx.y;
    const int t = threadIdx.x;
    __shared__ float sA[NH_][N_];
    __shared__ float sB[NH_][N_];
    __shared__ float w1[64], b1[8], w2[64], b2[8];
    if (t < 64) { w1[t] = th1w[t]; w2[t] = th2w[t]; }
    if (t < 8)  { b1[t] = th1b[t]; b2[t] = th2b[t]; }
    const size_t base = ((size_t)b * NH_) * N_ * N_ + (size_t)n * N_;
    for (int idx = t; idx < NH_ * N_; idx += 256) {
        int h = idx / N_, m = idx % N_;
        sA[h][m] = g_attn[base + (size_t)h * N_ * N_ + m];
    }
    __syncthreads();
    for (int idx = t; idx < NH_ * N_; idx += 256) {
        int h = idx / N_, m = idx % N_;
        float s = b1[h];
#pragma unroll
        for (int g = 0; g < 8; g++) s += w1[h * 8 + g] * sA[g][m];
        sB[h][m] = s;
    }
    __syncthreads();
    {   // warp w handles head w
        const int h = t >> 5, lane = t & 31;
        float mx = -1e30f;
        for (int m = lane; m < N_; m += 32) mx = fmaxf(mx, sB[h][m]);
#pragma unroll
        for (int o = 16; o; o >>= 1) mx = fmaxf(mx, __shfl_xor_sync(0xffffffffu, mx, o));
        float sum = 0.f;
        for (int m = lane; m < N_; m += 32) {
            float e = __expf(sB[h][m] - mx);
            sB[h][m] = e;
            sum += e;
        }
#pragma unroll
        for (int o = 16; o; o >>= 1) sum += __shfl_xor_sync(0xffffffffu, sum, o);
        float inv = 1.f / sum;
        for (int m = lane; m < N_; m += 32) sB[h][m] *= inv;
    }
    __syncthreads();
    for (int idx = t; idx < NH_ * N_; idx += 256) {
        int h = idx / N_, m = idx % N_;
        float s = b2[h];
#pragma unroll
        for (int g = 0; g < 8; g++) s += w2[h * 8 + g] * sB[g][m];
        g_attn[base + (size_t)h * N_ * N_ + m] = s;
    }
}

// ===================== K5: o = attn @ v, + vloc, relu =====================
// per (b,h): O(128 x 196) = V(128 x 196_m) @ attn^T(196_m x 196_n)
__global__ void __launch_bounds__(256) k_av()
{
    const int bh = blockIdx.y;
    const int b = bh >> 3, h = bh & 7;
    const int n0 = blockIdx.x * 64;
    const int t = threadIdx.x;
    __shared__ __align__(16) float As[16][132];
    __shared__ __align__(16) float Bs[16][68];
    float acc[8][4];
#pragma unroll
    for (int i = 0; i < 8; i++)
#pragma unroll
        for (int j = 0; j < 4; j++) acc[i][j] = 0.f;
    const int tym = t >> 4, txn = t & 15;
    const float* vp = g_v4  + ((size_t)b * CV + h * DV_) * N_;
    const float* ap = g_attn + (size_t)bh * N_ * N_;

    for (int k0 = 0; k0 < 208; k0 += 16) {
#pragma unroll
        for (int i = 0; i < 8; i++) {
            int idx = t + 256 * i;
            int mm = idx >> 4;     // d
            int kk = idx & 15;
            int k = k0 + kk;
            As[kk][mm] = (k < N_) ? vp[(size_t)mm * N_ + k] : 0.f;
        }
#pragma unroll
        for (int i = 0; i < 4; i++) {
            int idx = t + 256 * i;
            int nn = idx >> 4;     // 0..63
            int kk = idx & 15;
            int n = n0 + nn;
            int k = k0 + kk;
            Bs[kk][nn] = (n < N_ && k < N_) ? ap[(size_t)n * N_ + k] : 0.f;
        }
        __syncthreads();
#pragma unroll
        for (int kk = 0; kk < 16; kk++) {
            float4 a0 = *(const float4*)&As[kk][tym * 8];
            float4 a1 = *(const float4*)&As[kk][tym * 8 + 4];
            float4 b0 = *(const float4*)&Bs[kk][txn * 4];
            float a[8] = {a0.x, a0.y, a0.z, a0.w, a1.x, a1.y, a1.z, a1.w};
            float bb[4] = {b0.x, b0.y, b0.z, b0.w};
#pragma unroll
            for (int i = 0; i < 8; i++)
#pragma unroll
                for (int j = 0; j < 4; j++) acc[i][j] += a[i] * bb[j];
        }
        __syncthreads();
    }

#pragma unroll
    for (int i = 0; i < 8; i++) {
        int d = tym * 8 + i;
        int c = h * DV_ + d;
        const float* vl = g_vloc + ((size_t)b * CV + c) * N_;
        float* op       = g_oact + ((size_t)b * CV + c) * N_;
#pragma unroll
        for (int j = 0; j < 4; j++) {
            int n = n0 + txn * 4 + j;
            if (n < N_) {
                float v = acc[i][j] + vl[n];
                op[n] = v > 0.f ? v : 0.f;
            }
        }
    }
}

// ===================== K6: output projection GEMM =====================
// Out(384 x 196) = projw(384 x 1024) @ oact_b(1024 x 196) + projb
__global__ void __launch_bounds__(256) k_proj(
    const float* __restrict__ pw, const float* __restrict__ pb,
    float* __restrict__ out)
{
    const int b  = blockIdx.z;
    const int m0 = blockIdx.y * 128;
    const int n0 = blockIdx.x * 64;
    const int t  = threadIdx.x;
    __shared__ __align__(16) float As[16][132];
    __shared__ __align__(16) float Bs[16][68];
    float acc[8][4];
#pragma unroll
    for (int i = 0; i < 8; i++)
#pragma unroll
        for (int j = 0; j < 4; j++) acc[i][j] = 0.f;
    const int tym = t >> 4, txn = t & 15;
    const float* xb = g_oact + (size_t)b * CV * N_;

    for (int k0 = 0; k0 < CV; k0 += 16) {
#pragma unroll
        for (int i = 0; i < 8; i++) {
            int idx = t + 256 * i;
            int mm = idx >> 4;
            int kk = idx & 15;
            As[kk][mm] = pw[(size_t)(m0 + mm) * CV + k0 + kk];
        }
#pragma unroll
        for (int i = 0; i < 4; i++) {
            int idx = t + 256 * i;
            int nn = idx & 63;
            int kk = idx >> 6;
            int n  = n0 + nn;
            Bs[kk][nn] = (n < N_) ? xb[(size_t)(k0 + kk) * N_ + n] : 0.f;
        }
        __syncthreads();
#pragma unroll
        for (int kk = 0; kk < 16; kk++) {
            float4 a0 = *(const float4*)&As[kk][tym * 8];
            float4 a1 = *(const float4*)&As[kk][tym * 8 + 4];
            float4 b0 = *(const float4*)&Bs[kk][txn * 4];
            float a[8] = {a0.x, a0.y, a0.z, a0.w, a1.x, a1.y, a1.z, a1.w};
            float bb[4] = {b0.x, b0.y, b0.z, b0.w};
#pragma unroll
            for (int i = 0; i < 8; i++)
#pragma unroll
                for (int j = 0; j < 4; j++) acc[i][j] += a[i] * bb[j];
        }
        __syncthreads();
    }

#pragma unroll
    for (int i = 0; i < 8; i++) {
        int m = m0 + tym * 8 + i;
        float bias = pb[m];
        float* op = out + ((size_t)b * C_ + m) * N_;
#pragma unroll
        for (int j = 0; j < 4; j++) {
            int n = n0 + txn * 4 + j;
            if (n < N_) op[n] = acc[i][j] + bias;
        }
    }
}

// ===================== launch =====================
extern "C" void kernel_launch(void* const* d_in, const int* in_sizes, int n_in,
                              void* d_out, int out_size)
{
    const float* x    = (const float*)d_in[0];
    const float* qw   = (const float*)d_in[1];
    const float* qb   = (const float*)d_in[2];
    const float* kw   = (const float*)d_in[3];
    const float* kb   = (const float*)d_in[4];
    const float* vw   = (const float*)d_in[5];
    const float* vb   = (const float*)d_in[6];
    const float* vlw  = (const float*)d_in[7];
    const float* vlb  = (const float*)d_in[8];
    const float* th1w = (const float*)d_in[9];
    const float* th1b = (const float*)d_in[10];
    const float* th2w = (const float*)d_in[11];
    const float* th2b = (const float*)d_in[12];
    const float* pw   = (const float*)d_in[13];
    const float* pb   = (const float*)d_in[14];
    const float* bseg = (const float*)d_in[15];
    const int*   bidx = (const int*)d_in[16];
    float* out = (float*)d_out;

    k_qkv <<<dim3(4, 12, B_), 256>>>(x, qw, qb, kw, kb, vw, vb);
    k_dw  <<<dim3(B_ * CV), 224>>>(vlw, vlb);
    k_qk  <<<dim3(4, 4, B_ * NH_), 256>>>(bseg, bidx);
    k_ths <<<dim3(N_, B_), 256>>>(th1w, th1b, th2w, th2b);
    k_av  <<<dim3(4, B_ * NH_), 256>>>();
    k_proj<<<dim3(4, 3, B_), 256>>>(pw, pb, out);
}